// round 10
// baseline (speedup 1.0000x reference)
#include <cuda_runtime.h>
#include <math.h>

#define BB 8
#define CC 19
#define NN (512*1024)
#define NBS 3072              // s-bit buckets (padded): (bits(s)>>14) - BASES
#define NBS_USED 2144         // buckets reachable for s in [1,19]
#define BASES 0xFE00          // bits(1.0f) >> 14
#define K2T 1024
#define CHS 3                 // buckets per thread in k2 (1024*3 = 3072)
#define JB09 56               // bucket containing s = 1/0.9
#define JB09_T 18             // owning thread (56/3)
#define JB09_L 2              // local index (56 - 18*3)
#define FRAC09 0.8889         // fraction of bucket 56 with s < 1/0.9 (conf side)
#define NLL_SCALE 4194304.0f  // 2^22 fixed-point for nll
#define K2_BLOCKS (BB*CC)

// ---------------- static scratch (zero at load; self-cleaning per replay) ----
__device__ __align__(16) unsigned long long g_hist[BB*CC*NBS];  // 3.7 MB
__device__ double             g_sum;
__device__ unsigned long long g_cnt;
__device__ unsigned           g_done;

// ---------------- K1: softmax stats -> packed (count|nll) histogram ----------
__global__ __launch_bounds__(256, 4) void k1_stats(const float* __restrict__ pred) {
    int t = blockIdx.x * blockDim.x + threadIdx.x;   // float2 index within image
    int b = blockIdx.y;
    const float2* p = (const float2*)(pred + (size_t)b * CC * NN) + t;
    const int cs = NN / 2;

    float2 r[CC];
#pragma unroll
    for (int c = 0; c < CC; c++) r[c] = __ldcs(&p[c * cs]);

#define PROC(FIELD) { \
    float m = r[0].FIELD; \
    _Pragma("unroll") \
    for (int c = 1; c < CC; c++) m = fmaxf(m, r[c].FIELD); \
    int lab = 0; \
    float s = 0.0f; \
    _Pragma("unroll") \
    for (int c = CC - 1; c >= 0; c--) { \
        float x = r[c].FIELD; \
        s += __expf(x - m); \
        if (x == m) lab = c;              /* first occurrence wins */ \
    } \
    float nll = __logf(s);                /* -log(max_prob), in [0, log 19] */ \
    unsigned us = __float_as_uint(s); \
    int key = min(max((int)(us >> 14) - BASES, 0), NBS_USED - 1); \
    unsigned long long contrib = (1ull << 44) \
        | (unsigned long long)(unsigned)(nll * NLL_SCALE); \
    atomicAdd(&g_hist[((size_t)(b * CC + lab)) * NBS + key], contrib); }

    PROC(x) PROC(y)
#undef PROC
}

// ---------------- K2: per-(image,class) select + loss, fused finalize --------
// Bucket order: ascending s == DESCENDING prob. Top-k = lowest buckets.
// Case analysis (thr = rank-k crossing bucket):
//   thr > JB09 : conf set (prob>0.9) is a subset of top-k -> selection = top-k.
//   thr < JB09 : top-k is a subset of the conf set -> selection = conf set.
//   thr == JB09: union inside the bucket = max(need, frac*count) from low end.
__global__ __launch_bounds__(K2T) void k2_select(float* __restrict__ out) {
    const unsigned long long MASK44 = (1ull << 44) - 1ull;
    int bc = blockIdx.x;
    unsigned long long* h = &g_hist[(size_t)bc * NBS];
    int tid = threadIdx.x;
    int lane = tid & 31, wid = tid >> 5;
    int t0 = tid * CHS;

    // phase A0: coalesced stage into smem + coalesced zero of global slice
    __shared__ unsigned long long sm[NBS];        // 24 KB
#pragma unroll
    for (int j = 0; j < CHS; j++) {
        int idx = tid + j * K2T;
        sm[idx] = h[idx];
        h[idx] = 0ull;
    }
    __syncthreads();

    // phase A1: contiguous chunk from smem (packed add safe: no field overflow)
    unsigned long long hv[CHS];
    unsigned long long chunk = 0ull;
#pragma unroll
    for (int j = 0; j < CHS; j++) { hv[j] = sm[t0 + j]; chunk += hv[j]; }

    // hierarchical scan: warp-inclusive via shfl, then warp totals
    unsigned long long inc = chunk;
#pragma unroll
    for (int d = 1; d < 32; d <<= 1) {
        unsigned long long n = __shfl_up_sync(0xFFFFFFFFu, inc, d);
        if (lane >= d) inc += n;
    }
    __shared__ unsigned long long wtot[32];
    if (lane == 31) wtot[wid] = inc;
    __syncthreads();
    if (wid == 0) {
        unsigned long long w = wtot[lane];
#pragma unroll
        for (int d = 1; d < 32; d <<= 1) {
            unsigned long long n = __shfl_up_sync(0xFFFFFFFFu, w, d);
            if (lane >= d) w += n;
        }
        wtot[lane] = w;   // inclusive warp prefix
    }
    __syncthreads();
    unsigned long long warp_excl = (wid > 0) ? wtot[wid - 1] : 0ull;
    unsigned long long pre_pack = warp_excl + (inc - chunk);  // exclusive prefix
    long long total = (long long)(wtot[31] >> 44);
    long long k = (long long)(int)((float)total * 0.66f);  // fp32 trunc = reference

    __shared__ long long s_need, s_thrcnt, s_pcnt09, s_c09cnt;
    __shared__ unsigned long long s_ltnll, s_thrnll, s_pnll09, s_c09nll;
    __shared__ int s_thr;
    if (tid == 0) { s_thr = NBS; s_need = 0; s_thrcnt = 1; s_thrnll = 0; s_ltnll = 0; }
    __syncthreads();

    // phase B1: thread owning the rank-k crossing walks its registers
    long long pre_cnt = (long long)(pre_pack >> 44);
    long long ccnt    = (long long)(chunk >> 44);
    if (k > 0 && pre_cnt < k && pre_cnt + ccnt >= k) {
        long long cum = pre_cnt;
        unsigned long long ltn = pre_pack & MASK44;
#pragma unroll
        for (int j = 0; j < CHS; j++) {
            unsigned long long v = hv[j];
            long long c = (long long)(v >> 44);
            unsigned long long n = v & MASK44;
            if (cum < k && cum + c >= k) {
                s_thr = t0 + j; s_need = k - cum;
                s_thrcnt = (c > 0) ? c : 1; s_thrnll = n; s_ltnll = ltn;
                break;
            }
            ltn += n; cum += c;
        }
    }
    // phase B2: thread owning the 0.9-confidence bucket gathers conf-set stats
    if (tid == JB09_T) {
        long long pc = pre_cnt;
        unsigned long long pn = pre_pack & MASK44;
#pragma unroll
        for (int j = 0; j < JB09_L; j++) {
            pc += (long long)(hv[j] >> 44); pn += hv[j] & MASK44;
        }
        unsigned long long v09 = hv[JB09_L];
        s_pcnt09 = pc; s_pnll09 = pn;
        s_c09cnt = (long long)(v09 >> 44); s_c09nll = v09 & MASK44;
    }
    __syncthreads();

    if (tid == 0) {
        const double INV = 1.0 / (double)NLL_SCALE;
        long long cnt_sel = 0; double sum_sel = 0.0;
        if (k > 0 && s_thr > JB09) {
            // threshold prob < 0.9: conf set inside top-k -> selection = top-k
            double avg = (double)s_thrnll * INV / (double)s_thrcnt;
            cnt_sel = k;
            sum_sel = (double)s_ltnll * INV + (double)s_need * avg;
        } else if (k > 0 && s_thr == JB09) {
            // tie bucket straddles 0.9: union inside bucket from the low-s end
            double avg = (double)s_thrnll * INV / (double)s_thrcnt;
            double cA = FRAC09 * (double)s_thrcnt;
            double selt = fmax((double)s_need, cA);
            cnt_sel = (k - s_need) + (long long)(selt + 0.5);
            sum_sel = (double)s_ltnll * INV + selt * avg;
        } else {
            // k==0, or threshold prob > 0.9 (top-k inside conf set) -> conf set
            double cA = FRAC09 * (double)s_c09cnt;
            cnt_sel = s_pcnt09 + (long long)(cA + 0.5);
            sum_sel = ((double)s_pnll09 + FRAC09 * (double)s_c09nll) * INV;
        }
        if (cnt_sel > 0) {
            atomicAdd(&g_sum, sum_sel);
            atomicAdd(&g_cnt, (unsigned long long)cnt_sel);
        }
        __threadfence();
        unsigned ticket = atomicAdd(&g_done, 1);
        if (ticket == K2_BLOCKS - 1) {
            double             fs = atomicAdd(&g_sum, 0.0);
            unsigned long long fc = atomicAdd(&g_cnt, 0ull);
            if (fc == 0) fc = 1;
            out[0] = (float)(fs / (double)fc);
            g_sum = 0.0; g_cnt = 0ull; g_done = 0u;
        }
    }
}

// ---------------- launch ----------------
extern "C" void kernel_launch(void* const* d_in, const int* in_sizes, int n_in,
                              void* d_out, int out_size) {
    const float* pred = (const float*)d_in[0];
    float* out = (float*)d_out;

    {
        dim3 grid(NN / (256 * 2), BB);   // 1024 x 8
        k1_stats<<<grid, 256>>>(pred);
    }
    k2_select<<<K2_BLOCKS, K2T>>>(out);
}

// round 11
// speedup vs baseline: 1.1504x; 1.1504x over previous
#include <cuda_runtime.h>
#include <math.h>

#define BB 8
#define CC 19
#define NN (512*1024)
#define NBS 9216              // s-bit buckets (padded to 1024*9): (bits(s)>>12)-BASES
#define NBS_USED 8704         // buckets reachable for s in [1,19]
#define BASES 0x3F800         // bits(1.0f) >> 12
#define K2T 1024
#define CHS 9                 // buckets per thread in k2 (1024*9 = 9216)
#define JB09 227              // bucket containing s = 1/0.9
#define JB09_T 25             // owning thread (227/9)
#define JB09_L 2              // local index (227 - 25*9)
#define FRAC09 0.5556         // fraction of bucket 227 with s < 1/0.9 (conf side)
#define NLL_SCALE 4194304.0f  // 2^22 fixed-point for nll
#define K2_BLOCKS (BB*CC)
#define K2_SMEM (NBS*8)       // 72 KB dynamic smem

// ---------------- static scratch (zero at load; self-cleaning per replay) ----
__device__ __align__(16) unsigned long long g_hist[BB*CC*NBS];  // 11.2 MB
__device__ double             g_sum;
__device__ unsigned long long g_cnt;
__device__ unsigned           g_done;

// ---------------- K1: softmax stats -> packed (count|nll) histogram ----------
__global__ __launch_bounds__(256, 4) void k1_stats(const float* __restrict__ pred) {
    int t = blockIdx.x * blockDim.x + threadIdx.x;   // float2 index within image
    int b = blockIdx.y;
    const float2* p = (const float2*)(pred + (size_t)b * CC * NN) + t;
    const int cs = NN / 2;

    float2 r[CC];
#pragma unroll
    for (int c = 0; c < CC; c++) r[c] = __ldcs(&p[c * cs]);

#define PROC(FIELD) { \
    float m = r[0].FIELD; \
    _Pragma("unroll") \
    for (int c = 1; c < CC; c++) m = fmaxf(m, r[c].FIELD); \
    int lab = 0; \
    float s = 0.0f; \
    _Pragma("unroll") \
    for (int c = CC - 1; c >= 0; c--) { \
        float x = r[c].FIELD; \
        s += __expf(x - m); \
        if (x == m) lab = c;              /* first occurrence wins */ \
    } \
    float nll = __logf(s);                /* -log(max_prob), in [0, log 19] */ \
    unsigned us = __float_as_uint(s); \
    int key = min(max((int)(us >> 12) - BASES, 0), NBS_USED - 1); \
    unsigned long long contrib = (1ull << 44) \
        | (unsigned long long)(unsigned)(nll * NLL_SCALE); \
    atomicAdd(&g_hist[((size_t)(b * CC + lab)) * NBS + key], contrib); }

    PROC(x) PROC(y)
#undef PROC
}

// ---------------- K2: per-(image,class) select + loss, fused finalize --------
// Bucket order: ascending s == DESCENDING prob. Top-k = lowest buckets.
// Case analysis (thr = rank-k crossing bucket):
//   thr > JB09 : conf set (prob>0.9) is a subset of top-k -> selection = top-k.
//   thr < JB09 : top-k is a subset of the conf set -> selection = conf set.
//   thr == JB09: union inside the bucket = max(need, frac*count) from low end.
__global__ __launch_bounds__(K2T) void k2_select(float* __restrict__ out) {
    const unsigned long long MASK44 = (1ull << 44) - 1ull;
    extern __shared__ unsigned long long sm[];    // NBS entries (72 KB)
    int bc = blockIdx.x;
    unsigned long long* h = &g_hist[(size_t)bc * NBS];
    int tid = threadIdx.x;
    int lane = tid & 31, wid = tid >> 5;
    int t0 = tid * CHS;

    // phase A0: coalesced stage into smem + coalesced zero of global slice
#pragma unroll
    for (int j = 0; j < CHS; j++) {
        int idx = tid + j * K2T;
        sm[idx] = h[idx];
        h[idx] = 0ull;
    }
    __syncthreads();

    // phase A1: contiguous chunk from smem (packed add safe: no field overflow)
    unsigned long long hv[CHS];
    unsigned long long chunk = 0ull;
#pragma unroll
    for (int j = 0; j < CHS; j++) { hv[j] = sm[t0 + j]; chunk += hv[j]; }

    // hierarchical scan: warp-inclusive via shfl, then warp totals
    unsigned long long inc = chunk;
#pragma unroll
    for (int d = 1; d < 32; d <<= 1) {
        unsigned long long n = __shfl_up_sync(0xFFFFFFFFu, inc, d);
        if (lane >= d) inc += n;
    }
    __shared__ unsigned long long wtot[32];
    if (lane == 31) wtot[wid] = inc;
    __syncthreads();
    if (wid == 0) {
        unsigned long long w = wtot[lane];
#pragma unroll
        for (int d = 1; d < 32; d <<= 1) {
            unsigned long long n = __shfl_up_sync(0xFFFFFFFFu, w, d);
            if (lane >= d) w += n;
        }
        wtot[lane] = w;   // inclusive warp prefix
    }
    __syncthreads();
    unsigned long long warp_excl = (wid > 0) ? wtot[wid - 1] : 0ull;
    unsigned long long pre_pack = warp_excl + (inc - chunk);  // exclusive prefix
    long long total = (long long)(wtot[31] >> 44);
    long long k = (long long)(int)((float)total * 0.66f);  // fp32 trunc = reference

    __shared__ long long s_need, s_thrcnt, s_pcnt09, s_c09cnt;
    __shared__ unsigned long long s_ltnll, s_thrnll, s_pnll09, s_c09nll;
    __shared__ int s_thr;
    if (tid == 0) { s_thr = NBS; s_need = 0; s_thrcnt = 1; s_thrnll = 0; s_ltnll = 0; }
    __syncthreads();

    // phase B1: thread owning the rank-k crossing walks its registers
    long long pre_cnt = (long long)(pre_pack >> 44);
    long long ccnt    = (long long)(chunk >> 44);
    if (k > 0 && pre_cnt < k && pre_cnt + ccnt >= k) {
        long long cum = pre_cnt;
        unsigned long long ltn = pre_pack & MASK44;
#pragma unroll
        for (int j = 0; j < CHS; j++) {
            unsigned long long v = hv[j];
            long long c = (long long)(v >> 44);
            unsigned long long n = v & MASK44;
            if (cum < k && cum + c >= k) {
                s_thr = t0 + j; s_need = k - cum;
                s_thrcnt = (c > 0) ? c : 1; s_thrnll = n; s_ltnll = ltn;
                break;
            }
            ltn += n; cum += c;
        }
    }
    // phase B2: thread owning the 0.9-confidence bucket gathers conf-set stats
    if (tid == JB09_T) {
        long long pc = pre_cnt;
        unsigned long long pn = pre_pack & MASK44;
#pragma unroll
        for (int j = 0; j < JB09_L; j++) {
            pc += (long long)(hv[j] >> 44); pn += hv[j] & MASK44;
        }
        unsigned long long v09 = hv[JB09_L];
        s_pcnt09 = pc; s_pnll09 = pn;
        s_c09cnt = (long long)(v09 >> 44); s_c09nll = v09 & MASK44;
    }
    __syncthreads();

    if (tid == 0) {
        const double INV = 1.0 / (double)NLL_SCALE;
        long long cnt_sel = 0; double sum_sel = 0.0;
        if (k > 0 && s_thr > JB09) {
            // threshold prob < 0.9: conf set inside top-k -> selection = top-k
            double avg = (double)s_thrnll * INV / (double)s_thrcnt;
            cnt_sel = k;
            sum_sel = (double)s_ltnll * INV + (double)s_need * avg;
        } else if (k > 0 && s_thr == JB09) {
            // tie bucket straddles 0.9: union inside bucket from the low-s end
            double avg = (double)s_thrnll * INV / (double)s_thrcnt;
            double cA = FRAC09 * (double)s_thrcnt;
            double selt = fmax((double)s_need, cA);
            cnt_sel = (k - s_need) + (long long)(selt + 0.5);
            sum_sel = (double)s_ltnll * INV + selt * avg;
        } else {
            // k==0, or threshold prob > 0.9 (top-k inside conf set) -> conf set
            double cA = FRAC09 * (double)s_c09cnt;
            cnt_sel = s_pcnt09 + (long long)(cA + 0.5);
            sum_sel = ((double)s_pnll09 + FRAC09 * (double)s_c09nll) * INV;
        }
        if (cnt_sel > 0) {
            atomicAdd(&g_sum, sum_sel);
            atomicAdd(&g_cnt, (unsigned long long)cnt_sel);
        }
        __threadfence();
        unsigned ticket = atomicAdd(&g_done, 1);
        if (ticket == K2_BLOCKS - 1) {
            double             fs = atomicAdd(&g_sum, 0.0);
            unsigned long long fc = atomicAdd(&g_cnt, 0ull);
            if (fc == 0) fc = 1;
            out[0] = (float)(fs / (double)fc);
            g_sum = 0.0; g_cnt = 0ull; g_done = 0u;
        }
    }
}

// ---------------- launch ----------------
extern "C" void kernel_launch(void* const* d_in, const int* in_sizes, int n_in,
                              void* d_out, int out_size) {
    const float* pred = (const float*)d_in[0];
    float* out = (float*)d_out;

    static int attr_set = 0;
    if (!attr_set) {
        cudaFuncSetAttribute(k2_select,
                             cudaFuncAttributeMaxDynamicSharedMemorySize, K2_SMEM);
        attr_set = 1;
    }

    {
        dim3 grid(NN / (256 * 2), BB);   // 1024 x 8
        k1_stats<<<grid, 256>>>(pred);
    }
    k2_select<<<K2_BLOCKS, K2T, K2_SMEM>>>(out);
}

// round 12
// speedup vs baseline: 1.1550x; 1.0040x over previous
#include <cuda_runtime.h>
#include <math.h>

#define BB 8
#define CC 19
#define NN (512*1024)
#define NBS 10240             // s-bit buckets (padded to 1024*10): (bits(s)>>12)-BASES
#define NBS_USED 8704         // buckets reachable for s in [1,19]
#define BASES 0x3F800         // bits(1.0f) >> 12
#define K2T 1024
#define CHS 10                // buckets per thread in k2 (1024*10 = 10240)
#define JB09 227              // bucket containing s = 1/0.9
#define JB09_T 22             // owning thread (227/10)
#define JB09_L 7              // local index (227 - 22*10)
#define FRAC09 0.5556         // fraction of bucket 227 with s < 1/0.9 (conf side)
#define NLL_SCALE 4194304.0f  // 2^22 fixed-point for nll
#define K2_BLOCKS (BB*CC)
#define K2_SMEM (NBS*8)       // 80 KB dynamic smem

// ---------------- static scratch (zero at load; self-cleaning per replay) ----
__device__ __align__(16) unsigned long long g_hist[BB*CC*NBS];  // 12.5 MB
__device__ double             g_sum;
__device__ unsigned long long g_cnt;
__device__ unsigned           g_done;

// ---------------- K1: softmax stats -> packed (count|nll) histogram ----------
__global__ __launch_bounds__(256, 4) void k1_stats(const float* __restrict__ pred) {
    int t = blockIdx.x * blockDim.x + threadIdx.x;   // float2 index within image
    int b = blockIdx.y;
    const float2* p = (const float2*)(pred + (size_t)b * CC * NN) + t;
    const int cs = NN / 2;

    float2 r[CC];
#pragma unroll
    for (int c = 0; c < CC; c++) r[c] = __ldcs(&p[c * cs]);

#define PROC(FIELD) { \
    float m = r[0].FIELD; \
    _Pragma("unroll") \
    for (int c = 1; c < CC; c++) m = fmaxf(m, r[c].FIELD); \
    int lab = 0; \
    float s = 0.0f; \
    _Pragma("unroll") \
    for (int c = CC - 1; c >= 0; c--) { \
        float x = r[c].FIELD; \
        s += __expf(x - m); \
        if (x == m) lab = c;              /* first occurrence wins */ \
    } \
    float nll = __logf(s);                /* -log(max_prob), in [0, log 19] */ \
    unsigned us = __float_as_uint(s); \
    int key = min(max((int)(us >> 12) - BASES, 0), NBS_USED - 1); \
    unsigned long long contrib = (1ull << 44) \
        | (unsigned long long)(unsigned)(nll * NLL_SCALE); \
    atomicAdd(&g_hist[((size_t)(b * CC + lab)) * NBS + key], contrib); }

    PROC(x) PROC(y)
#undef PROC
}

// ---------------- K2: per-(image,class) select + loss, fused finalize --------
// Bucket order: ascending s == DESCENDING prob. Top-k = lowest buckets.
// Case analysis (thr = rank-k crossing bucket):
//   thr > JB09 : conf set (prob>0.9) is a subset of top-k -> selection = top-k.
//   thr < JB09 : top-k is a subset of the conf set -> selection = conf set.
//   thr == JB09: union inside the bucket = max(need, frac*count) from low end.
__global__ __launch_bounds__(K2T) void k2_select(float* __restrict__ out) {
    const unsigned long long MASK44 = (1ull << 44) - 1ull;
    extern __shared__ unsigned long long sm[];    // NBS entries (80 KB)
    int bc = blockIdx.x;
    unsigned long long* h = &g_hist[(size_t)bc * NBS];
    int tid = threadIdx.x;
    int lane = tid & 31, wid = tid >> 5;
    int t0 = tid * CHS;

    // phase A0: coalesced 16B stage into smem + coalesced 16B zero of global
    {
        ulonglong2* h2 = (ulonglong2*)h;
        ulonglong2* sm2 = (ulonglong2*)sm;
        ulonglong2 v[5];
#pragma unroll
        for (int j = 0; j < 5; j++) v[j] = h2[tid + j * K2T];   // MLP=5 x 16B
#pragma unroll
        for (int j = 0; j < 5; j++) sm2[tid + j * K2T] = v[j];
        ulonglong2 z; z.x = 0ull; z.y = 0ull;
#pragma unroll
        for (int j = 0; j < 5; j++) h2[tid + j * K2T] = z;
    }
    __syncthreads();

    // phase A1: contiguous chunk from smem (packed add safe: no field overflow)
    unsigned long long hv[CHS];
    unsigned long long chunk = 0ull;
#pragma unroll
    for (int j = 0; j < CHS; j++) { hv[j] = sm[t0 + j]; chunk += hv[j]; }

    // hierarchical scan: warp-inclusive via shfl, then warp totals
    unsigned long long inc = chunk;
#pragma unroll
    for (int d = 1; d < 32; d <<= 1) {
        unsigned long long n = __shfl_up_sync(0xFFFFFFFFu, inc, d);
        if (lane >= d) inc += n;
    }
    __shared__ unsigned long long wtot[32];
    if (lane == 31) wtot[wid] = inc;
    __syncthreads();
    if (wid == 0) {
        unsigned long long w = wtot[lane];
#pragma unroll
        for (int d = 1; d < 32; d <<= 1) {
            unsigned long long n = __shfl_up_sync(0xFFFFFFFFu, w, d);
            if (lane >= d) w += n;
        }
        wtot[lane] = w;   // inclusive warp prefix
    }
    __syncthreads();
    unsigned long long warp_excl = (wid > 0) ? wtot[wid - 1] : 0ull;
    unsigned long long pre_pack = warp_excl + (inc - chunk);  // exclusive prefix
    long long total = (long long)(wtot[31] >> 44);
    long long k = (long long)(int)((float)total * 0.66f);  // fp32 trunc = reference

    __shared__ long long s_need, s_thrcnt, s_pcnt09, s_c09cnt;
    __shared__ unsigned long long s_ltnll, s_thrnll, s_pnll09, s_c09nll;
    __shared__ int s_thr;
    if (tid == 0) { s_thr = NBS; s_need = 0; s_thrcnt = 1; s_thrnll = 0; s_ltnll = 0; }
    __syncthreads();

    // phase B1: thread owning the rank-k crossing walks its registers
    long long pre_cnt = (long long)(pre_pack >> 44);
    long long ccnt    = (long long)(chunk >> 44);
    if (k > 0 && pre_cnt < k && pre_cnt + ccnt >= k) {
        long long cum = pre_cnt;
        unsigned long long ltn = pre_pack & MASK44;
#pragma unroll
        for (int j = 0; j < CHS; j++) {
            unsigned long long v = hv[j];
            long long c = (long long)(v >> 44);
            unsigned long long n = v & MASK44;
            if (cum < k && cum + c >= k) {
                s_thr = t0 + j; s_need = k - cum;
                s_thrcnt = (c > 0) ? c : 1; s_thrnll = n; s_ltnll = ltn;
                break;
            }
            ltn += n; cum += c;
        }
    }
    // phase B2: thread owning the 0.9-confidence bucket gathers conf-set stats
    if (tid == JB09_T) {
        long long pc = pre_cnt;
        unsigned long long pn = pre_pack & MASK44;
#pragma unroll
        for (int j = 0; j < JB09_L; j++) {
            pc += (long long)(hv[j] >> 44); pn += hv[j] & MASK44;
        }
        unsigned long long v09 = hv[JB09_L];
        s_pcnt09 = pc; s_pnll09 = pn;
        s_c09cnt = (long long)(v09 >> 44); s_c09nll = v09 & MASK44;
    }
    __syncthreads();

    if (tid == 0) {
        const double INV = 1.0 / (double)NLL_SCALE;
        long long cnt_sel = 0; double sum_sel = 0.0;
        if (k > 0 && s_thr > JB09) {
            // threshold prob < 0.9: conf set inside top-k -> selection = top-k
            double avg = (double)s_thrnll * INV / (double)s_thrcnt;
            cnt_sel = k;
            sum_sel = (double)s_ltnll * INV + (double)s_need * avg;
        } else if (k > 0 && s_thr == JB09) {
            // tie bucket straddles 0.9: union inside bucket from the low-s end
            double avg = (double)s_thrnll * INV / (double)s_thrcnt;
            double cA = FRAC09 * (double)s_thrcnt;
            double selt = fmax((double)s_need, cA);
            cnt_sel = (k - s_need) + (long long)(selt + 0.5);
            sum_sel = (double)s_ltnll * INV + selt * avg;
        } else {
            // k==0, or threshold prob > 0.9 (top-k inside conf set) -> conf set
            double cA = FRAC09 * (double)s_c09cnt;
            cnt_sel = s_pcnt09 + (long long)(cA + 0.5);
            sum_sel = ((double)s_pnll09 + FRAC09 * (double)s_c09nll) * INV;
        }
        if (cnt_sel > 0) {
            atomicAdd(&g_sum, sum_sel);
            atomicAdd(&g_cnt, (unsigned long long)cnt_sel);
        }
        __threadfence();
        unsigned ticket = atomicAdd(&g_done, 1);
        if (ticket == K2_BLOCKS - 1) {
            double             fs = atomicAdd(&g_sum, 0.0);
            unsigned long long fc = atomicAdd(&g_cnt, 0ull);
            if (fc == 0) fc = 1;
            out[0] = (float)(fs / (double)fc);
            g_sum = 0.0; g_cnt = 0ull; g_done = 0u;
        }
    }
}

// ---------------- launch ----------------
extern "C" void kernel_launch(void* const* d_in, const int* in_sizes, int n_in,
                              void* d_out, int out_size) {
    const float* pred = (const float*)d_in[0];
    float* out = (float*)d_out;

    static int attr_set = 0;
    if (!attr_set) {
        cudaFuncSetAttribute(k2_select,
                             cudaFuncAttributeMaxDynamicSharedMemorySize, K2_SMEM);
        attr_set = 1;
    }

    {
        dim3 grid(NN / (256 * 2), BB);   // 1024 x 8
        k1_stats<<<grid, 256>>>(pred);
    }
    k2_select<<<K2_BLOCKS, K2T, K2_SMEM>>>(out);
}